// round 14
// baseline (speedup 1.0000x reference)
#include <cuda_runtime.h>
#include <cuda_bf16.h>
#include <cstdint>
#include <cstddef>

#define BN 32
#define LN 2048
#define TN 2047          // number of key timesteps (L-1)
#define HN 512
#define CC 32            // chunk size
#define NCH 64
#define NITEMS (BN * NCH)
#define EPSV 1e-6f
#define GP 33            // padded 32x32 stride

// Static device scratch (zero-initialized at module load; kernels restore
// g_flag/g_ctr to zero before exit so every graph replay sees a clean state)
__device__ float g_Tinv[BN * NCH * CC * CC];   // 8 MB
__device__ float g_beta[BN * NCH * CC];
__device__ int   g_flag[BN * NCH];
__device__ int   g_ctr;

__device__ __forceinline__ float warp_sum(float v) {
    v += __shfl_xor_sync(0xffffffffu, v, 16);
    v += __shfl_xor_sync(0xffffffffu, v, 8);
    v += __shfl_xor_sync(0xffffffffu, v, 4);
    v += __shfl_xor_sync(0xffffffffu, v, 2);
    v += __shfl_xor_sync(0xffffffffu, v, 1);
    return v;
}

// packed f32x2 FMA: d += a * b elementwise on two floats (PTX-only instruction)
__device__ __forceinline__ void fma2(unsigned long long& d,
                                     unsigned long long a,
                                     unsigned long long b) {
    asm("fma.rn.f32x2 %0, %1, %2, %0;" : "+l"(d) : "l"(a), "l"(b));
}

__device__ __forceinline__ void cp16cg(void* smem_dst, const void* gsrc) {
    unsigned sa = (unsigned)__cvta_generic_to_shared(smem_dst);
    asm volatile("cp.async.cg.shared.global [%0], [%1], 16;" :: "r"(sa), "l"(gsrc));
}
__device__ __forceinline__ void cp_commit() { asm volatile("cp.async.commit_group;"); }
__device__ __forceinline__ void cp_wait0()  { asm volatile("cp.async.wait_group 0;" ::: "memory"); }
__device__ __forceinline__ void cp_wait1()  { asm volatile("cp.async.wait_group 1;" ::: "memory"); }

// ---------------------------------------------------------------------------
// Phase A (R10 core + self-resetting counter): persistent pipelined gram.
// 116 CTAs x 512 threads, 1 CTA/SM.
// ---------------------------------------------------------------------------
__global__ void __launch_bounds__(512) gram_kernel(const float* __restrict__ hidden) {
    extern __shared__ float sm[];
    float* K0 = sm;                        // 32*512
    float* K1 = sm + CC * HN;              // 32*512
    float* G  = sm + 2 * CC * HN;          // 32*33 (lower: Gram; upper: prescaled L)
    __shared__ int sm_it;

    const int tid = threadIdx.x, wid = tid >> 5, lane = tid & 31;
    int ngrab = 0;                          // tid-0 only: grabs to undo at exit

    auto grab = [&]() -> int {
        if (tid == 0) { sm_it = atomicAdd(&g_ctr, 1); ngrab++; }
        __syncthreads();
        return sm_it;
    };
    auto prefetch = [&](int item, float* dst) {
        const int c = NCH - 1 - item / BN;
        const int b = item % BN;
        for (int idx = tid; idx < CC * (HN / 4); idx += 512) {
            int row = idx >> 7, col4 = idx & 127;
            int t = c * CC + (CC - 1) - row;
            float* dp = dst + row * HN + col4 * 4;
            if (t < TN) cp16cg(dp, hidden + (size_t)(b * LN + t) * HN + col4 * 4);
            else *reinterpret_cast<float4*>(dp) = make_float4(0.f, 0.f, 0.f, 0.f);
        }
    };

    int itA = grab();
    if (itA < NITEMS) prefetch(itA, K0);
    cp_commit();
    int pb = 0;

    while (itA < NITEMS) {
        int itB = grab();                       // contains a __syncthreads
        if (itB < NITEMS) prefetch(itB, pb ? K0 : K1);
        cp_commit();
        cp_wait1();                             // current tile ready
        __syncthreads();

        const ulonglong2* Ks2 = reinterpret_cast<const ulonglong2*>(pb ? K1 : K0);

        // ---- Gram: 36 4x4 lower-triangle blocks over 16 warps, f32x2 FMAs ----
        for (int blk = wid; blk < 36; blk += 16) {
            int BI = 0, rem = blk;
            while (rem > BI) { BI++; rem -= BI; }
            int BJ = rem;

            unsigned long long acc2[4][4];
            #pragma unroll
            for (int i = 0; i < 4; i++)
                #pragma unroll
                for (int j = 0; j < 4; j++) acc2[i][j] = 0ull;

            const ulonglong2* A2 = Ks2 + (4 * BI) * 128;
            const ulonglong2* B2 = Ks2 + (4 * BJ) * 128;
            #pragma unroll
            for (int stp = 0; stp < 4; stp++) {
                int hb = stp * 32 + lane;
                ulonglong2 av[4], bv[4];
                #pragma unroll
                for (int i = 0; i < 4; i++) av[i] = A2[i * 128 + hb];
                #pragma unroll
                for (int j = 0; j < 4; j++) bv[j] = B2[j * 128 + hb];
                #pragma unroll
                for (int i = 0; i < 4; i++)
                    #pragma unroll
                    for (int j = 0; j < 4; j++) {
                        fma2(acc2[i][j], av[i].x, bv[j].x);
                        fma2(acc2[i][j], av[i].y, bv[j].y);
                    }
            }
            #pragma unroll
            for (int i = 0; i < 4; i++)
                #pragma unroll
                for (int j = 0; j < 4; j++) {
                    float2 p = *reinterpret_cast<float2*>(&acc2[i][j]);
                    float v = warp_sum(p.x + p.y);
                    if (lane == i * 4 + j) G[(4 * BI + i) * GP + (4 * BJ + j)] = v;
                }
        }
        __syncthreads();

        const int c = NCH - 1 - itA / BN;
        const int b = itA % BN;

        // ---- fused beta + prescale: L[i][j] -> G[j*GP+i], beta -> gmem ----
        for (int e = tid; e < CC * CC; e += 512) {
            int i = e >> 5, j = e & 31;
            if (j < i) {
                float bt = 1.0f / (G[j * GP + j] + EPSV);
                G[j * GP + i] = G[i * GP + j] * bt;
            }
        }
        if (tid < CC)
            g_beta[(b * NCH + c) * CC + tid] = 1.0f / (G[tid * GP + tid] + EPSV);
        __syncthreads();

        // ---- single-warp register inversion (warp 0), immediate release ----
        if (wid == 0) {
            float x[CC];
            float* Tout = g_Tinv + (size_t)(b * NCH + c) * CC * CC;
            #pragma unroll
            for (int i = 0; i < CC; i++) {
                float a0 = 0.f, a1 = 0.f;
                #pragma unroll
                for (int j = 0; j < CC; j++) {
                    if (j < i) {
                        float t = G[j * GP + i] * x[j];   // prescaled L, broadcast LDS
                        if (j & 1) a1 -= t; else a0 -= t;
                    }
                }
                float xv = a0 + a1;
                x[i] = (i > lane) ? xv : ((i == lane) ? 1.f : 0.f);
                Tout[i * CC + lane] = x[i];
            }
            __syncwarp();
            __threadfence();
            if (lane == 0) atomicExch(&g_flag[b * NCH + c], 1);
        }
        __syncthreads();   // protect G reuse next iteration

        itA = itB;
        pb ^= 1;
    }
    // restore g_ctr to 0 for the next graph replay (sum of all grabs)
    if (tid == 0 && ngrab > 0) atomicSub(&g_ctr, ngrab);
}

// ---------------------------------------------------------------------------
// Phase B (R10 scan core) + flag self-reset + butterfly-reduced GEMV epilogue.
// grid BN, 512 threads.
// ---------------------------------------------------------------------------
__global__ void __launch_bounds__(512) scan_kernel(const float* __restrict__ hidden,
                                                   const float* __restrict__ W,
                                                   const float* __restrict__ bias,
                                                   float* __restrict__ out) {
    extern __shared__ float sm[];
    float*  Tb   = sm;                     // 2 * 32*32
    float*  btb  = Tb + 2 * CC * CC;       // 2 * 32
    float*  part = btb + 2 * CC;           // 16 * 33
    float*  ms   = part + 16 * 33;         // 32
    float2* ssb  = reinterpret_cast<float2*>(ms + CC);  // 32 float2
    int*    rdy  = reinterpret_cast<int*>(ssb + CC);
    float*  ctxs = sm + 2752;              // 512, 16B-aligned

    const int b = blockIdx.x;
    const int tid = threadIdx.x, wid = tid >> 5, lane = tid & 31;
    const float* hb = hidden + (size_t)b * LN * HN;

    float u = hb[(size_t)(LN - 1) * HN + tid];
    float racc = 0.f;

    float KA[CC], KB[CC];

    auto loadK = [&](int c, float (&Kr)[CC]) {
        #pragma unroll
        for (int j = 0; j < CC; j++) {
            int t = c * CC + (CC - 1) - j;
            Kr[j] = (t < TN) ? hb[(size_t)t * HN + tid] : 0.f;
        }
    };
    auto wait_flag = [&](int c) {
        if (tid == 0) {
            while (atomicAdd(&g_flag[b * NCH + c], 0) == 0) __nanosleep(64);
            __threadfence();
        }
        __syncthreads();
    };
    auto prefetch_T = [&](int c, int buf) {
        const float* Tsrc = g_Tinv + (size_t)(b * NCH + c) * CC * CC;
        float* Tdst = Tb + buf * (CC * CC);
        if (tid < CC * CC / 4)
            cp16cg(Tdst + tid * 4, Tsrc + tid * 4);
        else if (tid < CC * CC / 4 + CC / 4) {
            int q = tid - CC * CC / 4;
            cp16cg(btb + buf * CC + q * 4, g_beta + (size_t)(b * NCH + c) * CC + q * 4);
        }
        cp_commit();
    };

    auto chunk_body = [&](int c, const float (&K)[CC]) {
        const int buf = c & 1;
        if (c > 0 && tid == 0) {
            int f = atomicAdd(&g_flag[b * NCH + (c - 1)], 0);
            if (f) __threadfence();
            *rdy = f;
        }

        // step 1: fused multiply + butterfly transpose-reduce -> part[wid][lane]
        float t[16];
        {
            const bool h16 = (lane & 16) != 0;
            #pragma unroll
            for (int j = 0; j < 16; j++) {
                float give = (h16 ? K[j] : K[j + 16]) * u;
                float keep = (h16 ? K[j + 16] : K[j]) * u;
                t[j] = keep + __shfl_xor_sync(0xffffffffu, give, 16);
            }
            const bool h8 = (lane & 8) != 0;
            #pragma unroll
            for (int j = 0; j < 8; j++) {
                float give = h8 ? t[j] : t[j + 8];
                float keep = h8 ? t[j + 8] : t[j];
                t[j] = keep + __shfl_xor_sync(0xffffffffu, give, 8);
            }
            const bool h4 = (lane & 4) != 0;
            #pragma unroll
            for (int j = 0; j < 4; j++) {
                float give = h4 ? t[j] : t[j + 4];
                float keep = h4 ? t[j + 4] : t[j];
                t[j] = keep + __shfl_xor_sync(0xffffffffu, give, 4);
            }
            const bool h2 = (lane & 2) != 0;
            #pragma unroll
            for (int j = 0; j < 2; j++) {
                float give = h2 ? t[j] : t[j + 2];
                float keep = h2 ? t[j + 2] : t[j];
                t[j] = keep + __shfl_xor_sync(0xffffffffu, give, 2);
            }
            {
                const bool h1 = (lane & 1) != 0;
                float give = h1 ? t[0] : t[1];
                float keep = h1 ? t[1] : t[0];
                t[0] = keep + __shfl_xor_sync(0xffffffffu, give, 1);
            }
            part[wid * 33 + lane] = t[0];
        }
        cp_wait0();          // T(c)/beta copy done
        __syncthreads();     // B1: part + Tb/btb visible

        // T(c) consumed into smem -> reset its flag for the next graph replay
        if (tid == 0) atomicExch(&g_flag[b * NCH + c], 0);

        // warp 0: combine 16 warp partials -> m
        if (wid == 0) {
            float mm = 0.f;
            #pragma unroll
            for (int w = 0; w < 16; w++) mm += part[w * 33 + lane];
            ms[lane] = mm;
        }
        __syncthreads();     // B2: ms visible

        // step 2: s = Tinv * m ; store (s, beta*s) as float2
        {
            const float* Ti = Tb + buf * (CC * CC);
            const float* bt = btb + buf * CC;
            int r0 = wid, r1 = wid + 16;
            float mv = ms[lane];
            float a0 = Ti[r0 * CC + lane] * mv;
            float a1 = Ti[r1 * CC + lane] * mv;
            a0 = warp_sum(a0);
            a1 = warp_sum(a1);
            if (lane == 0) {
                ssb[r0] = make_float2(a0, a0 * bt[r0]);
                ssb[r1] = make_float2(a1, a1 * bt[r1]);
            }
        }
        __syncthreads();     // B3: ssb visible

        // step 3: u -= K^T sb ; ctx += K^T s (registers + broadcast LDS)
        #pragma unroll
        for (int j = 0; j < CC; j++) {
            float2 sv = ssb[j];
            racc += K[j] * sv.x;
            u    -= K[j] * sv.y;
        }

        if (c > 0) {
            if (*rdy) {
                prefetch_T(c - 1, buf ^ 1);
            } else {
                wait_flag(c - 1);
                prefetch_T(c - 1, buf ^ 1);
            }
        }
    };

    loadK(NCH - 1, KA);
    wait_flag(NCH - 1);
    prefetch_T(NCH - 1, (NCH - 1) & 1);

    for (int c = NCH - 1; c >= 1; c -= 2) {
        loadK(c - 1, KB);
        chunk_body(c, KA);
        if (c - 2 >= 0) loadK(c - 2, KA);
        chunk_body(c - 1, KB);
    }

    // ---- fused output GEMV with butterfly transpose-reduce ----
    ctxs[tid] = racc;
    __syncthreads();
    {
        const float4* c4 = reinterpret_cast<const float4*>(ctxs);
        const int row0 = wid * 32;

        float acc[32];
        #pragma unroll
        for (int r = 0; r < 32; r++) {
            const float4* w4 = reinterpret_cast<const float4*>(W + (size_t)(row0 + r) * HN);
            float a = 0.f;
            #pragma unroll
            for (int stp = 0; stp < 4; stp++) {
                int hbx = stp * 32 + lane;
                float4 wv = w4[hbx];
                float4 cv = c4[hbx];
                a += wv.x * cv.x + wv.y * cv.y + wv.z * cv.z + wv.w * cv.w;
            }
            acc[r] = a;
        }
        // butterfly transpose-reduce: lane l ends with full sum of row row0+l
        float t[16];
        const bool h16 = (lane & 16) != 0;
        #pragma unroll
        for (int j = 0; j < 16; j++) {
            float give = h16 ? acc[j] : acc[j + 16];
            float keep = h16 ? acc[j + 16] : acc[j];
            t[j] = keep + __shfl_xor_sync(0xffffffffu, give, 16);
        }
        const bool h8 = (lane & 8) != 0;
        #pragma unroll
        for (int j = 0; j < 8; j++) {
            float give = h8 ? t[j] : t[j + 8];
            float keep = h8 ? t[j + 8] : t[j];
            t[j] = keep + __shfl_xor_sync(0xffffffffu, give, 8);
        }
        const bool h4 = (lane & 4) != 0;
        #pragma unroll
        for (int j = 0; j < 4; j++) {
            float give = h4 ? t[j] : t[j + 4];
            float keep = h4 ? t[j + 4] : t[j];
            t[j] = keep + __shfl_xor_sync(0xffffffffu, give, 4);
        }
        const bool h2 = (lane & 2) != 0;
        #pragma unroll
        for (int j = 0; j < 2; j++) {
            float give = h2 ? t[j] : t[j + 2];
            float keep = h2 ? t[j + 2] : t[j];
            t[j] = keep + __shfl_xor_sync(0xffffffffu, give, 2);
        }
        {
            const bool h1 = (lane & 1) != 0;
            float give = h1 ? t[0] : t[1];
            float keep = h1 ? t[1] : t[0];
            t[0] = keep + __shfl_xor_sync(0xffffffffu, give, 1);
        }
        out[b * HN + row0 + lane] = t[0] + bias[row0 + lane];
    }
}

extern "C" void kernel_launch(void* const* d_in, const int* in_sizes, int n_in,
                              void* d_out, int out_size) {
    const float* hidden = (const float*)d_in[0];
    const float* W      = (const float*)d_in[1];
    const float* bias   = (const float*)d_in[2];
    float* out          = (float*)d_out;

    const int smA = (2 * CC * HN + CC * GP + 8) * (int)sizeof(float);   // ~133 KB
    const int smB = 100 * 1024;  // real ~15 KB; padded to keep gram off scan SMs

    static cudaStream_t s2 = nullptr;
    static cudaEvent_t evA = nullptr, evB = nullptr;
    if (!s2) {
        int lo = 0, hi = 0;
        cudaDeviceGetStreamPriorityRange(&lo, &hi);
        cudaStreamCreateWithPriority(&s2, cudaStreamNonBlocking, hi);
        cudaEventCreateWithFlags(&evA, cudaEventDisableTiming);
        cudaEventCreateWithFlags(&evB, cudaEventDisableTiming);
        cudaFuncSetAttribute(gram_kernel, cudaFuncAttributeMaxDynamicSharedMemorySize, smA);
        cudaFuncSetAttribute(scan_kernel, cudaFuncAttributeMaxDynamicSharedMemorySize, smB);
    }

    // fork directly: scan on s2 (flag-gated per chunk), gram on default stream.
    cudaEventRecord(evA, 0);
    cudaStreamWaitEvent(s2, evA, 0);
    scan_kernel<<<BN, 512, smB, s2>>>(hidden, W, bias, out);
    gram_kernel<<<116, 512, smA>>>(hidden);
    cudaEventRecord(evB, s2);
    cudaStreamWaitEvent(0, evB, 0);   // rejoin fork before capture ends
}

// round 15
// speedup vs baseline: 6.0250x; 6.0250x over previous
#include <cuda_runtime.h>
#include <cuda_bf16.h>
#include <cstdint>
#include <cstddef>

#define BN 32
#define LN 2048
#define TN 2047          // number of key timesteps (L-1)
#define HN 512
#define CC 32            // chunk size
#define NCH 64
#define NITEMS (BN * NCH)
#define EPSV 1e-6f
#define GP 33            // padded 32x32 stride
#define NGRAM 116

// Static device scratch (zero-initialized at load; kernels restore all sync
// state to zero before the graph replay ends: scan resets each flag after
// consuming it; the LAST gram CTA to exit resets g_ctr/g_done)
__device__ float g_Tinv[BN * NCH * CC * CC];   // 8 MB
__device__ float g_beta[BN * NCH * CC];
__device__ int   g_flag[BN * NCH];
__device__ int   g_ctr;
__device__ int   g_done;

__device__ __forceinline__ float warp_sum(float v) {
    v += __shfl_xor_sync(0xffffffffu, v, 16);
    v += __shfl_xor_sync(0xffffffffu, v, 8);
    v += __shfl_xor_sync(0xffffffffu, v, 4);
    v += __shfl_xor_sync(0xffffffffu, v, 2);
    v += __shfl_xor_sync(0xffffffffu, v, 1);
    return v;
}

// packed f32x2 FMA: d += a * b elementwise on two floats (PTX-only instruction)
__device__ __forceinline__ void fma2(unsigned long long& d,
                                     unsigned long long a,
                                     unsigned long long b) {
    asm("fma.rn.f32x2 %0, %1, %2, %0;" : "+l"(d) : "l"(a), "l"(b));
}

__device__ __forceinline__ void cp16cg(void* smem_dst, const void* gsrc) {
    unsigned sa = (unsigned)__cvta_generic_to_shared(smem_dst);
    asm volatile("cp.async.cg.shared.global [%0], [%1], 16;" :: "r"(sa), "l"(gsrc));
}
__device__ __forceinline__ void cp_commit() { asm volatile("cp.async.commit_group;"); }
__device__ __forceinline__ void cp_wait0()  { asm volatile("cp.async.wait_group 0;" ::: "memory"); }
__device__ __forceinline__ void cp_wait1()  { asm volatile("cp.async.wait_group 1;" ::: "memory"); }

// ---------------------------------------------------------------------------
// Phase A (R10 core): persistent pipelined gram. 116 CTAs x 512 threads.
// Counter reset: last CTA out restores g_ctr/g_done to 0 (race-free).
// ---------------------------------------------------------------------------
__global__ void __launch_bounds__(512) gram_kernel(const float* __restrict__ hidden) {
    extern __shared__ float sm[];
    float* K0 = sm;                        // 32*512
    float* K1 = sm + CC * HN;              // 32*512
    float* G  = sm + 2 * CC * HN;          // 32*33 (lower: Gram; upper: prescaled L)
    __shared__ int sm_it;

    const int tid = threadIdx.x, wid = tid >> 5, lane = tid & 31;

    auto grab = [&]() -> int {
        if (tid == 0) sm_it = atomicAdd(&g_ctr, 1);
        __syncthreads();
        return sm_it;
    };
    auto prefetch = [&](int item, float* dst) {
        const int c = NCH - 1 - item / BN;
        const int b = item % BN;
        for (int idx = tid; idx < CC * (HN / 4); idx += 512) {
            int row = idx >> 7, col4 = idx & 127;
            int t = c * CC + (CC - 1) - row;
            float* dp = dst + row * HN + col4 * 4;
            if (t < TN) cp16cg(dp, hidden + (size_t)(b * LN + t) * HN + col4 * 4);
            else *reinterpret_cast<float4*>(dp) = make_float4(0.f, 0.f, 0.f, 0.f);
        }
    };

    int itA = grab();
    if (itA < NITEMS) prefetch(itA, K0);
    cp_commit();
    int pb = 0;

    while (itA < NITEMS) {
        int itB = grab();                       // contains a __syncthreads
        if (itB < NITEMS) prefetch(itB, pb ? K0 : K1);
        cp_commit();
        cp_wait1();                             // current tile ready
        __syncthreads();

        const ulonglong2* Ks2 = reinterpret_cast<const ulonglong2*>(pb ? K1 : K0);

        // ---- Gram: 36 4x4 lower-triangle blocks over 16 warps, f32x2 FMAs ----
        for (int blk = wid; blk < 36; blk += 16) {
            int BI = 0, rem = blk;
            while (rem > BI) { BI++; rem -= BI; }
            int BJ = rem;

            unsigned long long acc2[4][4];
            #pragma unroll
            for (int i = 0; i < 4; i++)
                #pragma unroll
                for (int j = 0; j < 4; j++) acc2[i][j] = 0ull;

            const ulonglong2* A2 = Ks2 + (4 * BI) * 128;
            const ulonglong2* B2 = Ks2 + (4 * BJ) * 128;
            #pragma unroll
            for (int stp = 0; stp < 4; stp++) {
                int hb = stp * 32 + lane;
                ulonglong2 av[4], bv[4];
                #pragma unroll
                for (int i = 0; i < 4; i++) av[i] = A2[i * 128 + hb];
                #pragma unroll
                for (int j = 0; j < 4; j++) bv[j] = B2[j * 128 + hb];
                #pragma unroll
                for (int i = 0; i < 4; i++)
                    #pragma unroll
                    for (int j = 0; j < 4; j++) {
                        fma2(acc2[i][j], av[i].x, bv[j].x);
                        fma2(acc2[i][j], av[i].y, bv[j].y);
                    }
            }
            #pragma unroll
            for (int i = 0; i < 4; i++)
                #pragma unroll
                for (int j = 0; j < 4; j++) {
                    float2 p = *reinterpret_cast<float2*>(&acc2[i][j]);
                    float v = warp_sum(p.x + p.y);
                    if (lane == i * 4 + j) G[(4 * BI + i) * GP + (4 * BJ + j)] = v;
                }
        }
        __syncthreads();

        const int c = NCH - 1 - itA / BN;
        const int b = itA % BN;

        // ---- fused beta + prescale: L[i][j] -> G[j*GP+i], beta -> gmem ----
        for (int e = tid; e < CC * CC; e += 512) {
            int i = e >> 5, j = e & 31;
            if (j < i) {
                float bt = 1.0f / (G[j * GP + j] + EPSV);
                G[j * GP + i] = G[i * GP + j] * bt;
            }
        }
        if (tid < CC)
            g_beta[(b * NCH + c) * CC + tid] = 1.0f / (G[tid * GP + tid] + EPSV);
        __syncthreads();

        // ---- single-warp register inversion (warp 0), immediate release ----
        if (wid == 0) {
            float x[CC];
            float* Tout = g_Tinv + (size_t)(b * NCH + c) * CC * CC;
            #pragma unroll
            for (int i = 0; i < CC; i++) {
                float a0 = 0.f, a1 = 0.f;
                #pragma unroll
                for (int j = 0; j < CC; j++) {
                    if (j < i) {
                        float t = G[j * GP + i] * x[j];   // prescaled L, broadcast LDS
                        if (j & 1) a1 -= t; else a0 -= t;
                    }
                }
                float xv = a0 + a1;
                x[i] = (i > lane) ? xv : ((i == lane) ? 1.f : 0.f);
                Tout[i * CC + lane] = x[i];
            }
            __syncwarp();
            __threadfence();
            if (lane == 0) atomicExch(&g_flag[b * NCH + c], 1);
        }
        __syncthreads();   // protect G reuse next iteration

        itA = itB;
        pb ^= 1;
    }

    // last CTA out resets the counter for the next graph replay.
    // Every CTA reaches here only after its final grab, so no grabs can race.
    if (tid == 0) {
        int d = atomicAdd(&g_done, 1);
        if (d == NGRAM - 1) {
            atomicExch(&g_ctr, 0);
            atomicExch(&g_done, 0);
        }
    }
}

// ---------------------------------------------------------------------------
// Phase B (R10 scan core) + flag self-reset + butterfly-reduced GEMV epilogue.
// grid BN, 512 threads.
// ---------------------------------------------------------------------------
__global__ void __launch_bounds__(512) scan_kernel(const float* __restrict__ hidden,
                                                   const float* __restrict__ W,
                                                   const float* __restrict__ bias,
                                                   float* __restrict__ out) {
    extern __shared__ float sm[];
    float*  Tb   = sm;                     // 2 * 32*32
    float*  btb  = Tb + 2 * CC * CC;       // 2 * 32
    float*  part = btb + 2 * CC;           // 16 * 33
    float*  ms   = part + 16 * 33;         // 32
    float2* ssb  = reinterpret_cast<float2*>(ms + CC);  // 32 float2
    int*    rdy  = reinterpret_cast<int*>(ssb + CC);
    float*  ctxs = sm + 2752;              // 512, 16B-aligned

    const int b = blockIdx.x;
    const int tid = threadIdx.x, wid = tid >> 5, lane = tid & 31;
    const float* hb = hidden + (size_t)b * LN * HN;

    float u = hb[(size_t)(LN - 1) * HN + tid];
    float racc = 0.f;

    float KA[CC], KB[CC];

    auto loadK = [&](int c, float (&Kr)[CC]) {
        #pragma unroll
        for (int j = 0; j < CC; j++) {
            int t = c * CC + (CC - 1) - j;
            Kr[j] = (t < TN) ? hb[(size_t)t * HN + tid] : 0.f;
        }
    };
    auto wait_flag = [&](int c) {
        if (tid == 0) {
            while (atomicAdd(&g_flag[b * NCH + c], 0) == 0) __nanosleep(64);
            __threadfence();
        }
        __syncthreads();
    };
    auto prefetch_T = [&](int c, int buf) {
        const float* Tsrc = g_Tinv + (size_t)(b * NCH + c) * CC * CC;
        float* Tdst = Tb + buf * (CC * CC);
        if (tid < CC * CC / 4)
            cp16cg(Tdst + tid * 4, Tsrc + tid * 4);
        else if (tid < CC * CC / 4 + CC / 4) {
            int q = tid - CC * CC / 4;
            cp16cg(btb + buf * CC + q * 4, g_beta + (size_t)(b * NCH + c) * CC + q * 4);
        }
        cp_commit();
    };

    auto chunk_body = [&](int c, const float (&K)[CC]) {
        const int buf = c & 1;
        if (c > 0 && tid == 0) {
            int f = atomicAdd(&g_flag[b * NCH + (c - 1)], 0);
            if (f) __threadfence();
            *rdy = f;
        }

        // step 1: fused multiply + butterfly transpose-reduce -> part[wid][lane]
        float t[16];
        {
            const bool h16 = (lane & 16) != 0;
            #pragma unroll
            for (int j = 0; j < 16; j++) {
                float give = (h16 ? K[j] : K[j + 16]) * u;
                float keep = (h16 ? K[j + 16] : K[j]) * u;
                t[j] = keep + __shfl_xor_sync(0xffffffffu, give, 16);
            }
            const bool h8 = (lane & 8) != 0;
            #pragma unroll
            for (int j = 0; j < 8; j++) {
                float give = h8 ? t[j] : t[j + 8];
                float keep = h8 ? t[j + 8] : t[j];
                t[j] = keep + __shfl_xor_sync(0xffffffffu, give, 8);
            }
            const bool h4 = (lane & 4) != 0;
            #pragma unroll
            for (int j = 0; j < 4; j++) {
                float give = h4 ? t[j] : t[j + 4];
                float keep = h4 ? t[j + 4] : t[j];
                t[j] = keep + __shfl_xor_sync(0xffffffffu, give, 4);
            }
            const bool h2 = (lane & 2) != 0;
            #pragma unroll
            for (int j = 0; j < 2; j++) {
                float give = h2 ? t[j] : t[j + 2];
                float keep = h2 ? t[j + 2] : t[j];
                t[j] = keep + __shfl_xor_sync(0xffffffffu, give, 2);
            }
            {
                const bool h1 = (lane & 1) != 0;
                float give = h1 ? t[0] : t[1];
                float keep = h1 ? t[1] : t[0];
                t[0] = keep + __shfl_xor_sync(0xffffffffu, give, 1);
            }
            part[wid * 33 + lane] = t[0];
        }
        cp_wait0();          // T(c)/beta copy done
        __syncthreads();     // B1: part + Tb/btb visible

        // T(c) consumed into smem -> reset its flag for the next graph replay
        if (tid == 0) atomicExch(&g_flag[b * NCH + c], 0);

        // warp 0: combine 16 warp partials -> m
        if (wid == 0) {
            float mm = 0.f;
            #pragma unroll
            for (int w = 0; w < 16; w++) mm += part[w * 33 + lane];
            ms[lane] = mm;
        }
        __syncthreads();     // B2: ms visible

        // step 2: s = Tinv * m ; store (s, beta*s) as float2
        {
            const float* Ti = Tb + buf * (CC * CC);
            const float* bt = btb + buf * CC;
            int r0 = wid, r1 = wid + 16;
            float mv = ms[lane];
            float a0 = Ti[r0 * CC + lane] * mv;
            float a1 = Ti[r1 * CC + lane] * mv;
            a0 = warp_sum(a0);
            a1 = warp_sum(a1);
            if (lane == 0) {
                ssb[r0] = make_float2(a0, a0 * bt[r0]);
                ssb[r1] = make_float2(a1, a1 * bt[r1]);
            }
        }
        __syncthreads();     // B3: ssb visible

        // step 3: u -= K^T sb ; ctx += K^T s (registers + broadcast LDS)
        #pragma unroll
        for (int j = 0; j < CC; j++) {
            float2 sv = ssb[j];
            racc += K[j] * sv.x;
            u    -= K[j] * sv.y;
        }

        if (c > 0) {
            if (*rdy) {
                prefetch_T(c - 1, buf ^ 1);
            } else {
                wait_flag(c - 1);
                prefetch_T(c - 1, buf ^ 1);
            }
        }
    };

    loadK(NCH - 1, KA);
    wait_flag(NCH - 1);
    prefetch_T(NCH - 1, (NCH - 1) & 1);

    for (int c = NCH - 1; c >= 1; c -= 2) {
        loadK(c - 1, KB);
        chunk_body(c, KA);
        if (c - 2 >= 0) loadK(c - 2, KA);
        chunk_body(c - 1, KB);
    }

    // ---- fused output GEMV with butterfly transpose-reduce ----
    ctxs[tid] = racc;
    __syncthreads();
    {
        const float4* c4 = reinterpret_cast<const float4*>(ctxs);
        const int row0 = wid * 32;

        float acc[32];
        #pragma unroll
        for (int r = 0; r < 32; r++) {
            const float4* w4 = reinterpret_cast<const float4*>(W + (size_t)(row0 + r) * HN);
            float a = 0.f;
            #pragma unroll
            for (int stp = 0; stp < 4; stp++) {
                int hbx = stp * 32 + lane;
                float4 wv = w4[hbx];
                float4 cv = c4[hbx];
                a += wv.x * cv.x + wv.y * cv.y + wv.z * cv.z + wv.w * cv.w;
            }
            acc[r] = a;
        }
        // butterfly transpose-reduce: lane l ends with full sum of row row0+l
        float t[16];
        const bool h16 = (lane & 16) != 0;
        #pragma unroll
        for (int j = 0; j < 16; j++) {
            float give = h16 ? acc[j] : acc[j + 16];
            float keep = h16 ? acc[j + 16] : acc[j];
            t[j] = keep + __shfl_xor_sync(0xffffffffu, give, 16);
        }
        const bool h8 = (lane & 8) != 0;
        #pragma unroll
        for (int j = 0; j < 8; j++) {
            float give = h8 ? t[j] : t[j + 8];
            float keep = h8 ? t[j + 8] : t[j];
            t[j] = keep + __shfl_xor_sync(0xffffffffu, give, 8);
        }
        const bool h4 = (lane & 4) != 0;
        #pragma unroll
        for (int j = 0; j < 4; j++) {
            float give = h4 ? t[j] : t[j + 4];
            float keep = h4 ? t[j + 4] : t[j];
            t[j] = keep + __shfl_xor_sync(0xffffffffu, give, 4);
        }
        const bool h2 = (lane & 2) != 0;
        #pragma unroll
        for (int j = 0; j < 2; j++) {
            float give = h2 ? t[j] : t[j + 2];
            float keep = h2 ? t[j + 2] : t[j];
            t[j] = keep + __shfl_xor_sync(0xffffffffu, give, 2);
        }
        {
            const bool h1 = (lane & 1) != 0;
            float give = h1 ? t[0] : t[1];
            float keep = h1 ? t[1] : t[0];
            t[0] = keep + __shfl_xor_sync(0xffffffffu, give, 1);
        }
        out[b * HN + row0 + lane] = t[0] + bias[row0 + lane];
    }
}

extern "C" void kernel_launch(void* const* d_in, const int* in_sizes, int n_in,
                              void* d_out, int out_size) {
    const float* hidden = (const float*)d_in[0];
    const float* W      = (const float*)d_in[1];
    const float* bias   = (const float*)d_in[2];
    float* out          = (float*)d_out;

    const int smA = (2 * CC * HN + CC * GP + 8) * (int)sizeof(float);   // ~133 KB
    const int smB = 100 * 1024;  // real ~15 KB; padded to keep gram off scan SMs

    static cudaStream_t s2 = nullptr;
    static cudaEvent_t evA = nullptr, evB = nullptr;
    if (!s2) {
        int lo = 0, hi = 0;
        cudaDeviceGetStreamPriorityRange(&lo, &hi);
        cudaStreamCreateWithPriority(&s2, cudaStreamNonBlocking, hi);
        cudaEventCreateWithFlags(&evA, cudaEventDisableTiming);
        cudaEventCreateWithFlags(&evB, cudaEventDisableTiming);
        cudaFuncSetAttribute(gram_kernel, cudaFuncAttributeMaxDynamicSharedMemorySize, smA);
        cudaFuncSetAttribute(scan_kernel, cudaFuncAttributeMaxDynamicSharedMemorySize, smB);
    }

    // fork directly: scan on s2 (flag-gated per chunk), gram on default stream.
    cudaEventRecord(evA, 0);
    cudaStreamWaitEvent(s2, evA, 0);
    scan_kernel<<<BN, 512, smB, s2>>>(hidden, W, bias, out);
    gram_kernel<<<116, 512, smA>>>(hidden);
    cudaEventRecord(evB, s2);
    cudaStreamWaitEvent(0, evB, 0);   // rejoin fork before capture ends
}